// round 14
// baseline (speedup 1.0000x reference)
#include <cuda_runtime.h>
#include <cuda_fp16.h>
#include <cstdint>

#define SIZE  256
#define PREV  256
#define BATCH 32768

#define BM 128
#define BN 128
#define BK 32
#define NUM_KTILES (PREV / BK)       // 8
#define N_NTILES (BATCH / BN)        // 256
#define NCTA 148
#define HALF_CTAS (NCTA / 2)         // 74
#define NTHREADS 1024
#define FULL_TILES 3
#define TAIL_FIRST 222               // tiles 222..255 -> 68 half-tiles (n=64)

// ---------------- scratch ----------------
__device__ __align__(128) __half g_wa[PREV * SIZE];    // k-major [k][m]
__device__ __align__(128) __half g_wb[PREV * SIZE];
__device__ __align__(128) __half g_xh[PREV * BATCH];   // x as fp16, [k][n]
__device__ float g_c0[SIZE];
__device__ float g_cA[SIZE];
__device__ float g_cB[SIZE];
__device__ float g_cAB[SIZE];

// ---------------- smem layout ----------------
#define WKPAD 272
#define XBPAD 272
#define W_PROJ 69632                        // 256 k-rows x 272
#define OFF_X  (2 * W_PROJ)                 // 139264
#define X_STAGE 8704
#define X_NSTAGE 6
#define SMEM_TOTAL (OFF_X + X_NSTAGE * X_STAGE)   // 191488

// ============================ PTX helpers ============================
__device__ __forceinline__ uint32_t smem_u32(const void* p) {
    uint32_t a;
    asm("{ .reg .u64 t; cvta.to.shared.u64 t, %1; cvt.u32.u64 %0, t; }" : "=r"(a) : "l"(p));
    return a;
}
#define CP_ASYNC16(dst, src) \
    asm volatile("cp.async.cg.shared.global [%0], [%1], 16;" :: "r"(dst), "l"(src))
#define CP_COMMIT() asm volatile("cp.async.commit_group;" ::: "memory")
#define CP_WAIT1()  asm volatile("cp.async.wait_group 1;" ::: "memory")

#define LDSM_X4_T(r0, r1, r2, r3, addr)                                         \
    asm volatile("ldmatrix.sync.aligned.m8n8.x4.trans.shared.b16 {%0,%1,%2,%3}, [%4];" \
                 : "=r"(r0), "=r"(r1), "=r"(r2), "=r"(r3) : "r"(addr))

#define MMA_F16(c, a, b)                                                        \
    asm volatile("mma.sync.aligned.m16n8k16.row.col.f32.f16.f16.f32 "           \
                 "{%0,%1,%2,%3}, {%4,%5,%6,%7}, {%8,%9}, {%0,%1,%2,%3};"        \
                 : "+f"((c)[0]), "+f"((c)[1]), "+f"((c)[2]), "+f"((c)[3])       \
                 : "r"((a)[0]), "r"((a)[1]), "r"((a)[2]), "r"((a)[3]),          \
                   "r"((b)[0]), "r"((b)[1]))

// ---------------- prep: softmax (0..63) + coefs (64) + x->fp16 (rest) ----------------
__global__ void prep_kernel(const float* __restrict__ wa, const float* __restrict__ wb,
                            const float* __restrict__ wt, const float* __restrict__ x) {
    const int bx = blockIdx.x;
    if (bx < 64) {
        __shared__ unsigned short sh[PREV * 8];
        const int r0 = bx * 8;
        const float* src = (r0 < SIZE) ? wa : wb;
        __half* dst = (r0 < SIZE) ? g_wa : g_wb;
        const int m0 = r0 & (SIZE - 1);
        const int wid = threadIdx.x >> 5;
        const int lane = threadIdx.x & 31;

        const float* row = src + (size_t)(m0 + wid) * PREV;
        float v[8];
        float mx = -1e30f;
        #pragma unroll
        for (int i = 0; i < 8; i++) { v[i] = row[lane + 32 * i]; mx = fmaxf(mx, v[i]); }
        #pragma unroll
        for (int o = 16; o; o >>= 1) mx = fmaxf(mx, __shfl_xor_sync(0xffffffffu, mx, o));
        float e[8], s = 0.f;
        #pragma unroll
        for (int i = 0; i < 8; i++) { e[i] = expf(v[i] - mx); s += e[i]; }
        #pragma unroll
        for (int o = 16; o; o >>= 1) s += __shfl_xor_sync(0xffffffffu, s, o);
        const float inv = 1.0f / s;
        #pragma unroll
        for (int i = 0; i < 8; i++) {
            __half h = __float2half_rn(e[i] * inv);
            sh[(lane + 32 * i) * 8 + wid] = *(unsigned short*)&h;
        }
        __syncthreads();
        const int t = threadIdx.x;
        *(uint4*)&dst[(size_t)t * SIZE + m0] = *(uint4*)&sh[t * 8];
    } else if (bx == 64) {
        const int j = threadIdx.x;
        float p[16];
        float m = -1e30f;
        #pragma unroll
        for (int g = 0; g < 16; g++) { p[g] = wt[g * SIZE + j]; m = fmaxf(m, p[g]); }
        float ss = 0.f;
        #pragma unroll
        for (int g = 0; g < 16; g++) { p[g] = expf(p[g] - m); ss += p[g]; }
        const float iv = 1.0f / ss;
        #pragma unroll
        for (int g = 0; g < 16; g++) p[g] *= iv;
        g_c0[j]  = p[8] + p[9] + p[10] + p[11] + p[12] + p[13] + p[14] + p[15];
        g_cA[j]  = p[2] + p[3] + p[6] + p[7] - p[8] - p[9] - p[12] - p[13];
        g_cB[j]  = p[4] + p[5] + p[6] + p[7] - p[8] - p[9] - p[10] - p[11];
        g_cAB[j] = p[1] - p[2] - p[4] - 2.f * p[6] - p[7]
                 + p[8] + 2.f * p[9] + p[11] + p[13] - p[14];
    } else {
        const size_t i = ((size_t)(bx - 65) * 256 + threadIdx.x) * 8;
        float4 a = *(const float4*)(x + i);
        float4 b = *(const float4*)(x + i + 4);
        __half2 h0 = __floats2half2_rn(a.x, a.y);
        __half2 h1 = __floats2half2_rn(a.z, a.w);
        __half2 h2 = __floats2half2_rn(b.x, b.y);
        __half2 h3 = __floats2half2_rn(b.z, b.w);
        uint4 o;
        o.x = *(uint32_t*)&h0; o.y = *(uint32_t*)&h1;
        o.z = *(uint32_t*)&h2; o.w = *(uint32_t*)&h3;
        *(uint4*)(g_xh + i) = o;
    }
}
#define PREP_BLOCKS (65 + (PREV * BATCH) / (256 * 8))   // 65 + 4096

// ---------------- main kernel: 1024 threads, 32 warps (8m x 4n), warp tile 16m x 32n ----------------
__global__ void __launch_bounds__(NTHREADS, 1)
fused_logic_mma_kernel(const __half* __restrict__ xh, float* __restrict__ out) {
    extern __shared__ char smem[];
    const uint32_t sb = smem_u32(smem);
    const int tid = threadIdx.x;
    const int wid = tid >> 5;
    const int lane = tid & 31;
    const int warp_m = wid >> 2;      // 0..7  (16 m rows each)
    const int warp_n = wid & 3;       // 0..3  (32 n cols each)
    const int bid = blockIdx.x;
    const int m0 = (bid & 1) * BM;
    const int nbase = bid >> 1;       // 0..73

    const int Q = FULL_TILES * NUM_KTILES;     // 24, uniform
    const bool has_tail = (nbase < 68);
    const int tn0 = (TAIL_FIRST + (nbase >> 1)) * BN + (nbase & 1) * 64;

    float accA[4][4];
    float accB[4][4];
    #pragma unroll
    for (int nt = 0; nt < 4; nt++)
        #pragma unroll
        for (int e = 0; e < 4; e++) { accA[nt][e] = 0.f; accB[nt][e] = 0.f; }

    // X tile issue (full width): threads 0..511 own one 16B chunk each
    const int xk = (tid >> 4) & 31;
    const int xc = tid & 15;
    auto issue_x = [&](int q) {
        if (tid < 512) {
            const int n0 = (nbase + (q >> 3) * HALF_CTAS) * BN;
            const char* src = (const char*)(xh + (size_t)((q & 7) * BK + xk) * BATCH + n0 + xc * 8);
            CP_ASYNC16(sb + OFF_X + (q % X_NSTAGE) * X_STAGE + xk * XBPAD + xc * 16, src);
        }
    };
    // tail (n=64): threads 0..255, 8 chunks per row
    auto issue_x_tail = [&](int t) {
        if (tid < 256) {
            const int k = tid >> 3;
            const int c = tid & 7;
            const char* src = (const char*)(xh + (size_t)(t * BK + k) * BATCH + tn0 + c * 8);
            CP_ASYNC16(sb + OFF_X + (t % X_NSTAGE) * X_STAGE + k * XBPAD + c * 16, src);
        }
    };

    // ---- prologue: W + X0,X1 (group A); X2,X3 (group B) ----
    {
        #pragma unroll 4
        for (int i = 0; i < 8; i++) {
            int flat = tid + i * NTHREADS;
            int v = flat >> 12, rem = flat & 4095, k = rem >> 4, c = rem & 15;
            const __half* wp = v ? g_wb : g_wa;
            const char* src = (const char*)(wp + (size_t)k * SIZE + m0 + c * 8);
            CP_ASYNC16(sb + v * W_PROJ + k * WKPAD + c * 16, src);
        }
        issue_x(0); issue_x(1);
        CP_COMMIT();
        issue_x(2); issue_x(3);
        CP_COMMIT();
    }

    // ldmatrix per-lane address components
    const int g8 = lane >> 3;
    const int r8 = lane & 7;
    // W (A frag, m16): k-rows in (g8>>1), m-chunk in (g8&1); warp_m covers 16 m = 32B
    const uint32_t w_off = (uint32_t)(((g8 >> 1) * 8 + r8) * WKPAD + (g8 & 1) * 16 + warp_m * 32);
    const uint32_t x_off = (uint32_t)(((g8 & 1) * 8 + r8) * XBPAD + (g8 >> 1) * 16 + warp_n * 64);
    const uint32_t x_off_tail = (uint32_t)(((g8 & 1) * 8 + r8) * XBPAD + (g8 >> 1) * 16 + warp_n * 32);

    auto epilogue = [&](int n0, int ntmax) {
        const int row_in = lane >> 2;
        const int col2 = (lane & 3) * 2;
        const int nstride = (ntmax == 4) ? 32 : 16;
        const int j1 = m0 + warp_m * 16 + row_in;
        const int j2 = j1 + 8;
        const float c0a = g_c0[j1], cAa = g_cA[j1], cBa = g_cB[j1], cXa = g_cAB[j1];
        const float c0b = g_c0[j2], cAb = g_cA[j2], cBb = g_cB[j2], cXb = g_cAB[j2];
        #pragma unroll
        for (int nt = 0; nt < 4; nt++) {
            if (nt >= ntmax) break;
            const int n = n0 + warp_n * nstride + nt * 8 + col2;
            float2 o1, o2;
            {
                float A = accA[nt][0], B = accB[nt][0];
                o1.x = fmaf(cXa * A, B, fmaf(cAa, A, fmaf(cBa, B, c0a)));
                A = accA[nt][1]; B = accB[nt][1];
                o1.y = fmaf(cXa * A, B, fmaf(cAa, A, fmaf(cBa, B, c0a)));
            }
            {
                float A = accA[nt][2], B = accB[nt][2];
                o2.x = fmaf(cXb * A, B, fmaf(cAb, A, fmaf(cBb, B, c0b)));
                A = accA[nt][3]; B = accB[nt][3];
                o2.y = fmaf(cXb * A, B, fmaf(cAb, A, fmaf(cBb, B, c0b)));
            }
            *(float2*)&out[(size_t)j1 * BATCH + n] = o1;
            *(float2*)&out[(size_t)j2 * BATCH + n] = o2;
            #pragma unroll
            for (int e = 0; e < 4; e++) { accA[nt][e] = 0.f; accB[nt][e] = 0.f; }
        }
    };

    auto body = [&](int q) {
        const int kt = q & 7;
        const uint32_t xbase = sb + OFF_X + (q % X_NSTAGE) * X_STAGE;
        const uint32_t wkbase = sb + (uint32_t)(kt * BK) * WKPAD + w_off;

        #pragma unroll
        for (int ks = 0; ks < 2; ks++) {
            uint32_t xf[4][2];
            #pragma unroll
            for (int j = 0; j < 2; j++) {
                const uint32_t xo = xbase + x_off + ks * 16 * XBPAD + j * 32;
                uint32_t a0, a1, a2, a3;
                LDSM_X4_T(a0, a1, a2, a3, xo);
                xf[2 * j][0] = a0; xf[2 * j][1] = a1;
                xf[2 * j + 1][0] = a2; xf[2 * j + 1][1] = a3;
            }
            uint32_t fa[4], fb[4];
            const uint32_t ao = wkbase + ks * 16 * WKPAD;
            LDSM_X4_T(fa[0], fa[1], fa[2], fa[3], ao);
            LDSM_X4_T(fb[0], fb[1], fb[2], fb[3], ao + W_PROJ);
            #pragma unroll
            for (int nt = 0; nt < 4; nt++) MMA_F16(accA[nt], fa, xf[nt]);
            #pragma unroll
            for (int nt = 0; nt < 4; nt++) MMA_F16(accB[nt], fb, xf[nt]);
        }
        if (kt == 7) epilogue((nbase + (q >> 3) * HALF_CTAS) * BN, 4);
    };

    auto body_tail = [&](int t) {
        const uint32_t xbase = sb + OFF_X + (t % X_NSTAGE) * X_STAGE;
        const uint32_t wkbase = sb + (uint32_t)(t * BK) * WKPAD + w_off;

        #pragma unroll
        for (int ks = 0; ks < 2; ks++) {
            uint32_t xf[2][2];
            {
                const uint32_t xo = xbase + x_off_tail + ks * 16 * XBPAD;
                uint32_t a0, a1, a2, a3;
                LDSM_X4_T(a0, a1, a2, a3, xo);
                xf[0][0] = a0; xf[0][1] = a1;
                xf[1][0] = a2; xf[1][1] = a3;
            }
            uint32_t fa[4], fb[4];
            const uint32_t ao = wkbase + ks * 16 * WKPAD;
            LDSM_X4_T(fa[0], fa[1], fa[2], fa[3], ao);
            LDSM_X4_T(fb[0], fb[1], fb[2], fb[3], ao + W_PROJ);
            #pragma unroll
            for (int nt = 0; nt < 2; nt++) MMA_F16(accA[nt], fa, xf[nt]);
            #pragma unroll
            for (int nt = 0; nt < 2; nt++) MMA_F16(accB[nt], fb, xf[nt]);
        }
        if (t == 7) epilogue(tn0, 2);
    };

    // ---- main loop: pairs, one wait + one barrier per 2 steps ----
    #pragma unroll 1
    for (int q = 0; q < Q; q += 2) {
        CP_WAIT1();
        __syncthreads();
        if (q + 4 < Q) issue_x(q + 4);
        else if (has_tail) issue_x_tail(q + 4 - Q);
        if (q + 5 < Q) issue_x(q + 5);
        else if (has_tail) issue_x_tail(q + 5 - Q);
        CP_COMMIT();
        body(q);
        body(q + 1);
    }

    if (!has_tail) return;

    // ---- tail: 8 half-steps; 24 % 6 == 0 keeps ring slots aligned (t -> t % 6) ----
    #pragma unroll 1
    for (int t = 0; t < 8; t += 2) {
        CP_WAIT1();
        __syncthreads();
        if (t + 4 < 8) issue_x_tail(t + 4);
        if (t + 5 < 8) issue_x_tail(t + 5);
        CP_COMMIT();
        body_tail(t);
        body_tail(t + 1);
    }
}

// ---------------- launch ----------------
extern "C" void kernel_launch(void* const* d_in, const int* in_sizes, int n_in,
                              void* d_out, int out_size) {
    const float* x  = (const float*)d_in[0];   // [PREV,  BATCH]
    const float* wa = (const float*)d_in[1];   // [SIZE,  PREV]
    const float* wb = (const float*)d_in[2];   // [SIZE,  PREV]
    const float* wt = (const float*)d_in[3];   // [16,    SIZE]
    float* out = (float*)d_out;                // [SIZE,  BATCH]

    cudaFuncSetAttribute(fused_logic_mma_kernel,
                         cudaFuncAttributeMaxDynamicSharedMemorySize, SMEM_TOTAL);

    prep_kernel<<<PREP_BLOCKS, 256>>>(wa, wb, wt, x);

    void* xh_dev;
    cudaGetSymbolAddress(&xh_dev, g_xh);
    fused_logic_mma_kernel<<<NCTA, NTHREADS, SMEM_TOTAL>>>((const __half*)xh_dev, out);
}

// round 15
// speedup vs baseline: 1.0945x; 1.0945x over previous
#include <cuda_runtime.h>
#include <cuda_fp16.h>
#include <cstdint>

#define SIZE  256
#define PREV  256
#define BATCH 32768

#define BM 128
#define BN 128
#define BK 32
#define NUM_KTILES (PREV / BK)       // 8
#define N_NTILES (BATCH / BN)        // 256
#define NCTA 148
#define HALF_CTAS (NCTA / 2)         // 74
#define NTHREADS 512
#define FULL_TILES 3
#define TAIL_FIRST 222               // tiles 222..255 -> 68 half-tiles (n=64)
#define Q_FULL (FULL_TILES * NUM_KTILES)   // 24

// ---------------- scratch ----------------
__device__ __align__(128) __half g_wa[PREV * SIZE];    // k-major [k][m]
__device__ __align__(128) __half g_wb[PREV * SIZE];
__device__ __align__(128) __half g_xh[PREV * BATCH];   // x as fp16, [k][n]
__device__ float g_c0[SIZE];
__device__ float g_cA[SIZE];
__device__ float g_cB[SIZE];
__device__ float g_cAB[SIZE];

// ---------------- smem layout ----------------
#define WKPAD 272
#define XBPAD 272
#define W_PROJ 69632                        // 256 k-rows x 272
#define OFF_X  (2 * W_PROJ)                 // 139264
#define X_STAGE 8704
#define X_NSTAGE 8
#define SMEM_TOTAL (OFF_X + X_NSTAGE * X_STAGE)   // 208896 (= 204 KB <= 227 KB cap)

// ============================ PTX helpers ============================
__device__ __forceinline__ uint32_t smem_u32(const void* p) {
    uint32_t a;
    asm("{ .reg .u64 t; cvta.to.shared.u64 t, %1; cvt.u32.u64 %0, t; }" : "=r"(a) : "l"(p));
    return a;
}
#define CP_ASYNC16(dst, src) \
    asm volatile("cp.async.cg.shared.global [%0], [%1], 16;" :: "r"(dst), "l"(src))
#define CP_COMMIT() asm volatile("cp.async.commit_group;" ::: "memory")
#define CP_WAIT0()  asm volatile("cp.async.wait_group 0;" ::: "memory")

#define LDSM_X4_T(r0, r1, r2, r3, addr)                                         \
    asm volatile("ldmatrix.sync.aligned.m8n8.x4.trans.shared.b16 {%0,%1,%2,%3}, [%4];" \
                 : "=r"(r0), "=r"(r1), "=r"(r2), "=r"(r3) : "r"(addr))

#define MMA_F16(c, a, b)                                                        \
    asm volatile("mma.sync.aligned.m16n8k16.row.col.f32.f16.f16.f32 "           \
                 "{%0,%1,%2,%3}, {%4,%5,%6,%7}, {%8,%9}, {%0,%1,%2,%3};"        \
                 : "+f"((c)[0]), "+f"((c)[1]), "+f"((c)[2]), "+f"((c)[3])       \
                 : "r"((a)[0]), "r"((a)[1]), "r"((a)[2]), "r"((a)[3]),          \
                   "r"((b)[0]), "r"((b)[1]))

// ---------------- prep: softmax (0..63) + coefs (64) + x->fp16 (rest) ----------------
__global__ void prep_kernel(const float* __restrict__ wa, const float* __restrict__ wb,
                            const float* __restrict__ wt, const float* __restrict__ x) {
    const int bx = blockIdx.x;
    if (bx < 64) {
        __shared__ unsigned short sh[PREV * 8];
        const int r0 = bx * 8;
        const float* src = (r0 < SIZE) ? wa : wb;
        __half* dst = (r0 < SIZE) ? g_wa : g_wb;
        const int m0 = r0 & (SIZE - 1);
        const int wid = threadIdx.x >> 5;
        const int lane = threadIdx.x & 31;

        const float* row = src + (size_t)(m0 + wid) * PREV;
        float v[8];
        float mx = -1e30f;
        #pragma unroll
        for (int i = 0; i < 8; i++) { v[i] = row[lane + 32 * i]; mx = fmaxf(mx, v[i]); }
        #pragma unroll
        for (int o = 16; o; o >>= 1) mx = fmaxf(mx, __shfl_xor_sync(0xffffffffu, mx, o));
        float e[8], s = 0.f;
        #pragma unroll
        for (int i = 0; i < 8; i++) { e[i] = expf(v[i] - mx); s += e[i]; }
        #pragma unroll
        for (int o = 16; o; o >>= 1) s += __shfl_xor_sync(0xffffffffu, s, o);
        const float inv = 1.0f / s;
        #pragma unroll
        for (int i = 0; i < 8; i++) {
            __half h = __float2half_rn(e[i] * inv);
            sh[(lane + 32 * i) * 8 + wid] = *(unsigned short*)&h;
        }
        __syncthreads();
        const int t = threadIdx.x;
        *(uint4*)&dst[(size_t)t * SIZE + m0] = *(uint4*)&sh[t * 8];
    } else if (bx == 64) {
        const int j = threadIdx.x;
        float p[16];
        float m = -1e30f;
        #pragma unroll
        for (int g = 0; g < 16; g++) { p[g] = wt[g * SIZE + j]; m = fmaxf(m, p[g]); }
        float ss = 0.f;
        #pragma unroll
        for (int g = 0; g < 16; g++) { p[g] = expf(p[g] - m); ss += p[g]; }
        const float iv = 1.0f / ss;
        #pragma unroll
        for (int g = 0; g < 16; g++) p[g] *= iv;
        g_c0[j]  = p[8] + p[9] + p[10] + p[11] + p[12] + p[13] + p[14] + p[15];
        g_cA[j]  = p[2] + p[3] + p[6] + p[7] - p[8] - p[9] - p[12] - p[13];
        g_cB[j]  = p[4] + p[5] + p[6] + p[7] - p[8] - p[9] - p[10] - p[11];
        g_cAB[j] = p[1] - p[2] - p[4] - 2.f * p[6] - p[7]
                 + p[8] + 2.f * p[9] + p[11] + p[13] - p[14];
    } else {
        const size_t i = ((size_t)(bx - 65) * 256 + threadIdx.x) * 8;
        float4 a = *(const float4*)(x + i);
        float4 b = *(const float4*)(x + i + 4);
        __half2 h0 = __floats2half2_rn(a.x, a.y);
        __half2 h1 = __floats2half2_rn(a.z, a.w);
        __half2 h2 = __floats2half2_rn(b.x, b.y);
        __half2 h3 = __floats2half2_rn(b.z, b.w);
        uint4 o;
        o.x = *(uint32_t*)&h0; o.y = *(uint32_t*)&h1;
        o.z = *(uint32_t*)&h2; o.w = *(uint32_t*)&h3;
        *(uint4*)(g_xh + i) = o;
    }
}
#define PREP_BLOCKS (65 + (PREV * BATCH) / (256 * 8))   // 65 + 4096

// ---------------- main kernel: 512 thr, 16 warps (4x4), 8-stage ring, barrier per QUAD ----------------
__global__ void __launch_bounds__(NTHREADS, 1)
fused_logic_mma_kernel(const __half* __restrict__ xh, float* __restrict__ out) {
    extern __shared__ char smem[];
    const uint32_t sb = smem_u32(smem);
    const int tid = threadIdx.x;
    const int wid = tid >> 5;
    const int lane = tid & 31;
    const int warp_m = wid >> 2;      // 0..3
    const int warp_n = wid & 3;       // 0..3
    const int bid = blockIdx.x;
    const int m0 = (bid & 1) * BM;
    const int nbase = bid >> 1;       // 0..73

    const bool has_tail = (nbase < 68);
    const int tn0 = (TAIL_FIRST + (nbase >> 1)) * BN + (nbase & 1) * 64;

    float accA[2][4][4];
    float accB[2][4][4];
    #pragma unroll
    for (int mt = 0; mt < 2; mt++)
        #pragma unroll
        for (int nt = 0; nt < 4; nt++)
            #pragma unroll
            for (int e = 0; e < 4; e++) { accA[mt][nt][e] = 0.f; accB[mt][nt][e] = 0.f; }

    // unified stage issue: s < Q_FULL -> full 128n; Q_FULL..Q_FULL+7 -> tail 64n
    const int xk = tid >> 4;
    const int xc = tid & 15;
    auto issue_stage = [&](int s) {
        if (s < Q_FULL) {
            const int n0 = (nbase + (s >> 3) * HALF_CTAS) * BN;
            const char* src = (const char*)(xh + (size_t)((s & 7) * BK + xk) * BATCH + n0 + xc * 8);
            CP_ASYNC16(sb + OFF_X + (s & 7) * X_STAGE + xk * XBPAD + xc * 16, src);
        } else if (has_tail && s < Q_FULL + 8) {
            const int t = s - Q_FULL;
            if (xc < 8) {
                const char* src = (const char*)(xh + (size_t)(t * BK + xk) * BATCH + tn0 + xc * 8);
                CP_ASYNC16(sb + OFF_X + (s & 7) * X_STAGE + xk * XBPAD + xc * 16, src);
            }
        }
    };

    // ---- prologue: one group = W + stages 0..3 ----
    {
        #pragma unroll 4
        for (int i = 0; i < 16; i++) {
            int flat = tid + i * NTHREADS;
            int v = flat >> 12, rem = flat & 4095, k = rem >> 4, c = rem & 15;
            const __half* wp = v ? g_wb : g_wa;
            const char* src = (const char*)(wp + (size_t)k * SIZE + m0 + c * 8);
            CP_ASYNC16(sb + v * W_PROJ + k * WKPAD + c * 16, src);
        }
        issue_stage(0); issue_stage(1); issue_stage(2); issue_stage(3);
        CP_COMMIT();
    }

    // ldmatrix per-lane address components
    const int g8 = lane >> 3;
    const int r8 = lane & 7;
    const uint32_t w_off = (uint32_t)(((g8 >> 1) * 8 + r8) * WKPAD + (g8 & 1) * 16 + warp_m * 64);
    const uint32_t x_off = (uint32_t)(((g8 & 1) * 8 + r8) * XBPAD + (g8 >> 1) * 16 + warp_n * 64);
    const uint32_t x_off_tail = (uint32_t)(((g8 & 1) * 8 + r8) * XBPAD + (g8 >> 1) * 16 + warp_n * 32);

    auto epilogue = [&](int n0, int ntmax) {
        const int row_in = lane >> 2;
        const int col2 = (lane & 3) * 2;
        const int nstride = (ntmax == 4) ? 32 : 16;
        #pragma unroll
        for (int mt = 0; mt < 2; mt++) {
            const int j1 = m0 + warp_m * 32 + mt * 16 + row_in;
            const int j2 = j1 + 8;
            const float c0a = g_c0[j1], cAa = g_cA[j1], cBa = g_cB[j1], cXa = g_cAB[j1];
            const float c0b = g_c0[j2], cAb = g_cA[j2], cBb = g_cB[j2], cXb = g_cAB[j2];
            #pragma unroll
            for (int nt = 0; nt < 4; nt++) {
                if (nt >= ntmax) break;
                const int n = n0 + warp_n * nstride + nt * 8 + col2;
                float2 o1, o2;
                {
                    float A = accA[mt][nt][0], B = accB[mt][nt][0];
                    o1.x = fmaf(cXa * A, B, fmaf(cAa, A, fmaf(cBa, B, c0a)));
                    A = accA[mt][nt][1]; B = accB[mt][nt][1];
                    o1.y = fmaf(cXa * A, B, fmaf(cAa, A, fmaf(cBa, B, c0a)));
                }
                {
                    float A = accA[mt][nt][2], B = accB[mt][nt][2];
                    o2.x = fmaf(cXb * A, B, fmaf(cAb, A, fmaf(cBb, B, c0b)));
                    A = accA[mt][nt][3]; B = accB[mt][nt][3];
                    o2.y = fmaf(cXb * A, B, fmaf(cAb, A, fmaf(cBb, B, c0b)));
                }
                *(float2*)&out[(size_t)j1 * BATCH + n] = o1;
                *(float2*)&out[(size_t)j2 * BATCH + n] = o2;
                #pragma unroll
                for (int e = 0; e < 4; e++) { accA[mt][nt][e] = 0.f; accB[mt][nt][e] = 0.f; }
            }
        }
    };

    auto body = [&](int q) {
        const int kt = q & 7;
        const uint32_t xbase = sb + OFF_X + (q & 7) * X_STAGE;
        const uint32_t wkbase = sb + (uint32_t)(kt * BK) * WKPAD + w_off;

        #pragma unroll
        for (int ks = 0; ks < 2; ks++) {
            uint32_t xf[4][2];
            #pragma unroll
            for (int j = 0; j < 2; j++) {
                const uint32_t xo = xbase + x_off + ks * 16 * XBPAD + j * 32;
                uint32_t a0, a1, a2, a3;
                LDSM_X4_T(a0, a1, a2, a3, xo);
                xf[2 * j][0] = a0; xf[2 * j][1] = a1;
                xf[2 * j + 1][0] = a2; xf[2 * j + 1][1] = a3;
            }
            uint32_t fa[2][4], fb[2][4];
            #pragma unroll
            for (int mt = 0; mt < 2; mt++) {
                const uint32_t ao = wkbase + ks * 16 * WKPAD + mt * 32;
                LDSM_X4_T(fa[mt][0], fa[mt][1], fa[mt][2], fa[mt][3], ao);
                LDSM_X4_T(fb[mt][0], fb[mt][1], fb[mt][2], fb[mt][3], ao + W_PROJ);
            }
            #pragma unroll
            for (int mt = 0; mt < 2; mt++) {
                #pragma unroll
                for (int nt = 0; nt < 4; nt++) MMA_F16(accA[mt][nt], fa[mt], xf[nt]);
                #pragma unroll
                for (int nt = 0; nt < 4; nt++) MMA_F16(accB[mt][nt], fb[mt], xf[nt]);
            }
        }
        if (kt == 7) epilogue((nbase + (q >> 3) * HALF_CTAS) * BN, 4);
    };

    auto body_tail = [&](int t) {
        const uint32_t xbase = sb + OFF_X + (t & 7) * X_STAGE;   // (Q_FULL + t) & 7 == t & 7
        const uint32_t wkbase = sb + (uint32_t)(t * BK) * WKPAD + w_off;

        #pragma unroll
        for (int ks = 0; ks < 2; ks++) {
            uint32_t xf[2][2];
            {
                const uint32_t xo = xbase + x_off_tail + ks * 16 * XBPAD;
                uint32_t a0, a1, a2, a3;
                LDSM_X4_T(a0, a1, a2, a3, xo);
                xf[0][0] = a0; xf[0][1] = a1;
                xf[1][0] = a2; xf[1][1] = a3;
            }
            uint32_t fa[2][4], fb[2][4];
            #pragma unroll
            for (int mt = 0; mt < 2; mt++) {
                const uint32_t ao = wkbase + ks * 16 * WKPAD + mt * 32;
                LDSM_X4_T(fa[mt][0], fa[mt][1], fa[mt][2], fa[mt][3], ao);
                LDSM_X4_T(fb[mt][0], fb[mt][1], fb[mt][2], fb[mt][3], ao + W_PROJ);
            }
            #pragma unroll
            for (int mt = 0; mt < 2; mt++) {
                #pragma unroll
                for (int nt = 0; nt < 2; nt++) MMA_F16(accA[mt][nt], fa[mt], xf[nt]);
                #pragma unroll
                for (int nt = 0; nt < 2; nt++) MMA_F16(accB[mt][nt], fb[mt], xf[nt]);
            }
        }
        if (t == 7) epilogue(tn0, 2);
    };

    // ---- main loop: QUADS. One wait + one barrier per 4 steps. ----
    // Invariant at quad top: the single outstanding group (stages q0..q0+3,
    // issued one quad earlier) is drained by WAIT0; barrier certifies all
    // threads finished reading stages q0-4..q0-1, freeing slots (q0+4)%8...
    #pragma unroll 1
    for (int q0 = 0; q0 < Q_FULL; q0 += 4) {
        CP_WAIT0();
        __syncthreads();
        issue_stage(q0 + 4); issue_stage(q0 + 5);
        issue_stage(q0 + 6); issue_stage(q0 + 7);
        CP_COMMIT();
        body(q0); body(q0 + 1); body(q0 + 2); body(q0 + 3);
    }

    if (!has_tail) return;

    // ---- tail: 2 quads of half-steps (stages Q_FULL..Q_FULL+7 -> slots t&7) ----
    CP_WAIT0();
    __syncthreads();
    issue_stage(Q_FULL + 4); issue_stage(Q_FULL + 5);
    issue_stage(Q_FULL + 6); issue_stage(Q_FULL + 7);
    CP_COMMIT();
    body_tail(0); body_tail(1); body_tail(2); body_tail(3);

    CP_WAIT0();
    __syncthreads();
    body_tail(4); body_tail(5); body_tail(6); body_tail(7);
}

// ---------------- launch ----------------
extern "C" void kernel_launch(void* const* d_in, const int* in_sizes, int n_in,
                              void* d_out, int out_size) {
    const float* x  = (const float*)d_in[0];   // [PREV,  BATCH]
    const float* wa = (const float*)d_in[1];   // [SIZE,  PREV]
    const float* wb = (const float*)d_in[2];   // [SIZE,  PREV]
    const float* wt = (const float*)d_in[3];   // [16,    SIZE]
    float* out = (float*)d_out;                // [SIZE,  BATCH]

    cudaFuncSetAttribute(fused_logic_mma_kernel,
                         cudaFuncAttributeMaxDynamicSharedMemorySize, SMEM_TOTAL);

    prep_kernel<<<PREP_BLOCKS, 256>>>(wa, wb, wt, x);

    void* xh_dev;
    cudaGetSymbolAddress(&xh_dev, g_xh);
    fused_logic_mma_kernel<<<NCTA, NTHREADS, SMEM_TOTAL>>>((const __half*)xh_dev, out);
}

// round 16
// speedup vs baseline: 1.1053x; 1.0099x over previous
#include <cuda_runtime.h>
#include <cuda_fp16.h>
#include <cstdint>

#define SIZE  256
#define PREV  256
#define BATCH 32768

#define BM 128
#define BN 128
#define BK 32
#define NUM_KTILES (PREV / BK)       // 8
#define N_NTILES (BATCH / BN)        // 256
#define NCTA 148
#define HALF_CTAS (NCTA / 2)         // 74
#define NTHREADS 512
#define FULL_TILES 3
#define TAIL_FIRST 222               // tiles 222..255 -> 68 half-tiles (n=64)
#define Q_FULL (FULL_TILES * NUM_KTILES)   // 24

// ---------------- scratch ----------------
__device__ __align__(128) __half g_wa[PREV * SIZE];    // k-major [k][m]
__device__ __align__(128) __half g_wb[PREV * SIZE];
__device__ __align__(128) __half g_xh[PREV * BATCH];   // x as fp16, [k][n]
__device__ float g_c0[SIZE];
__device__ float g_cA[SIZE];
__device__ float g_cB[SIZE];
__device__ float g_cAB[SIZE];

// ---------------- smem layout ----------------
#define WKPAD 272
#define XBPAD 272
#define W_PROJ 69632                        // 256 k-rows x 272
#define OFF_X  (2 * W_PROJ)                 // 139264
#define X_STAGE 8704
#define X_NSTAGE 8
#define SMEM_TOTAL (OFF_X + X_NSTAGE * X_STAGE)   // 208896

// ============================ PTX helpers ============================
__device__ __forceinline__ uint32_t smem_u32(const void* p) {
    uint32_t a;
    asm("{ .reg .u64 t; cvta.to.shared.u64 t, %1; cvt.u32.u64 %0, t; }" : "=r"(a) : "l"(p));
    return a;
}
#define CP_ASYNC16(dst, src) \
    asm volatile("cp.async.cg.shared.global [%0], [%1], 16;" :: "r"(dst), "l"(src))
#define CP_COMMIT() asm volatile("cp.async.commit_group;" ::: "memory")
#define CP_WAIT0()  asm volatile("cp.async.wait_group 0;" ::: "memory")

#define LDSM_X4_T(r0, r1, r2, r3, addr)                                         \
    asm volatile("ldmatrix.sync.aligned.m8n8.x4.trans.shared.b16 {%0,%1,%2,%3}, [%4];" \
                 : "=r"(r0), "=r"(r1), "=r"(r2), "=r"(r3) : "r"(addr))

#define MMA_F16(c, a, b)                                                        \
    asm volatile("mma.sync.aligned.m16n8k16.row.col.f32.f16.f16.f32 "           \
                 "{%0,%1,%2,%3}, {%4,%5,%6,%7}, {%8,%9}, {%0,%1,%2,%3};"        \
                 : "+f"((c)[0]), "+f"((c)[1]), "+f"((c)[2]), "+f"((c)[3])       \
                 : "r"((a)[0]), "r"((a)[1]), "r"((a)[2]), "r"((a)[3]),          \
                   "r"((b)[0]), "r"((b)[1]))

// ---------------- prep: softmax (0..63) + coefs (64) + x->fp16 (rest) ----------------
__global__ void prep_kernel(const float* __restrict__ wa, const float* __restrict__ wb,
                            const float* __restrict__ wt, const float* __restrict__ x) {
    const int bx = blockIdx.x;
    if (bx < 64) {
        __shared__ unsigned short sh[PREV * 8];
        const int r0 = bx * 8;
        const float* src = (r0 < SIZE) ? wa : wb;
        __half* dst = (r0 < SIZE) ? g_wa : g_wb;
        const int m0 = r0 & (SIZE - 1);
        const int wid = threadIdx.x >> 5;
        const int lane = threadIdx.x & 31;

        const float* row = src + (size_t)(m0 + wid) * PREV;
        float v[8];
        float mx = -1e30f;
        #pragma unroll
        for (int i = 0; i < 8; i++) { v[i] = row[lane + 32 * i]; mx = fmaxf(mx, v[i]); }
        #pragma unroll
        for (int o = 16; o; o >>= 1) mx = fmaxf(mx, __shfl_xor_sync(0xffffffffu, mx, o));
        float e[8], s = 0.f;
        #pragma unroll
        for (int i = 0; i < 8; i++) { e[i] = expf(v[i] - mx); s += e[i]; }
        #pragma unroll
        for (int o = 16; o; o >>= 1) s += __shfl_xor_sync(0xffffffffu, s, o);
        const float inv = 1.0f / s;
        #pragma unroll
        for (int i = 0; i < 8; i++) {
            __half h = __float2half_rn(e[i] * inv);
            sh[(lane + 32 * i) * 8 + wid] = *(unsigned short*)&h;
        }
        __syncthreads();
        const int t = threadIdx.x;
        *(uint4*)&dst[(size_t)t * SIZE + m0] = *(uint4*)&sh[t * 8];
    } else if (bx == 64) {
        const int j = threadIdx.x;
        float p[16];
        float m = -1e30f;
        #pragma unroll
        for (int g = 0; g < 16; g++) { p[g] = wt[g * SIZE + j]; m = fmaxf(m, p[g]); }
        float ss = 0.f;
        #pragma unroll
        for (int g = 0; g < 16; g++) { p[g] = expf(p[g] - m); ss += p[g]; }
        const float iv = 1.0f / ss;
        #pragma unroll
        for (int g = 0; g < 16; g++) p[g] *= iv;
        g_c0[j]  = p[8] + p[9] + p[10] + p[11] + p[12] + p[13] + p[14] + p[15];
        g_cA[j]  = p[2] + p[3] + p[6] + p[7] - p[8] - p[9] - p[12] - p[13];
        g_cB[j]  = p[4] + p[5] + p[6] + p[7] - p[8] - p[9] - p[10] - p[11];
        g_cAB[j] = p[1] - p[2] - p[4] - 2.f * p[6] - p[7]
                 + p[8] + 2.f * p[9] + p[11] + p[13] - p[14];
    } else {
        const size_t i = ((size_t)(bx - 65) * 256 + threadIdx.x) * 8;
        float4 a = *(const float4*)(x + i);
        float4 b = *(const float4*)(x + i + 4);
        __half2 h0 = __floats2half2_rn(a.x, a.y);
        __half2 h1 = __floats2half2_rn(a.z, a.w);
        __half2 h2 = __floats2half2_rn(b.x, b.y);
        __half2 h3 = __floats2half2_rn(b.z, b.w);
        uint4 o;
        o.x = *(uint32_t*)&h0; o.y = *(uint32_t*)&h1;
        o.z = *(uint32_t*)&h2; o.w = *(uint32_t*)&h3;
        *(uint4*)(g_xh + i) = o;
    }
}
#define PREP_BLOCKS (65 + (PREV * BATCH) / (256 * 8))   // 65 + 4096

// ---------------- main kernel: 512 thr, 8-stage ring, quad barriers, WARP-SKEWED step order ----------------
__global__ void __launch_bounds__(NTHREADS, 1)
fused_logic_mma_kernel(const __half* __restrict__ xh, float* __restrict__ out) {
    extern __shared__ char smem[];
    const uint32_t sb = smem_u32(smem);
    const int tid = threadIdx.x;
    const int wid = tid >> 5;
    const int lane = tid & 31;
    const int warp_m = wid >> 2;      // 0..3 (also the per-SMSP skew: warps on one SMSP have distinct warp_m)
    const int warp_n = wid & 3;       // 0..3
    const int bid = blockIdx.x;
    const int m0 = (bid & 1) * BM;
    const int nbase = bid >> 1;       // 0..73

    const bool has_tail = (nbase < 68);
    const int tn0 = (TAIL_FIRST + (nbase >> 1)) * BN + (nbase & 1) * 64;

    float accA[2][4][4];
    float accB[2][4][4];
    #pragma unroll
    for (int mt = 0; mt < 2; mt++)
        #pragma unroll
        for (int nt = 0; nt < 4; nt++)
            #pragma unroll
            for (int e = 0; e < 4; e++) { accA[mt][nt][e] = 0.f; accB[mt][nt][e] = 0.f; }

    // unified stage issue: s < Q_FULL -> full 128n; Q_FULL..Q_FULL+7 -> tail 64n
    const int xk = tid >> 4;
    const int xc = tid & 15;
    auto issue_stage = [&](int s) {
        if (s < Q_FULL) {
            const int n0 = (nbase + (s >> 3) * HALF_CTAS) * BN;
            const char* src = (const char*)(xh + (size_t)((s & 7) * BK + xk) * BATCH + n0 + xc * 8);
            CP_ASYNC16(sb + OFF_X + (s & 7) * X_STAGE + xk * XBPAD + xc * 16, src);
        } else if (has_tail && s < Q_FULL + 8) {
            const int t = s - Q_FULL;
            if (xc < 8) {
                const char* src = (const char*)(xh + (size_t)(t * BK + xk) * BATCH + tn0 + xc * 8);
                CP_ASYNC16(sb + OFF_X + (s & 7) * X_STAGE + xk * XBPAD + xc * 16, src);
            }
        }
    };

    // ---- prologue: one group = W + stages 0..3 ----
    {
        #pragma unroll 4
        for (int i = 0; i < 16; i++) {
            int flat = tid + i * NTHREADS;
            int v = flat >> 12, rem = flat & 4095, k = rem >> 4, c = rem & 15;
            const __half* wp = v ? g_wb : g_wa;
            const char* src = (const char*)(wp + (size_t)k * SIZE + m0 + c * 8);
            CP_ASYNC16(sb + v * W_PROJ + k * WKPAD + c * 16, src);
        }
        issue_stage(0); issue_stage(1); issue_stage(2); issue_stage(3);
        CP_COMMIT();
    }

    // ldmatrix per-lane address components
    const int g8 = lane >> 3;
    const int r8 = lane & 7;
    const uint32_t w_off = (uint32_t)(((g8 >> 1) * 8 + r8) * WKPAD + (g8 & 1) * 16 + warp_m * 64);
    const uint32_t x_off = (uint32_t)(((g8 & 1) * 8 + r8) * XBPAD + (g8 >> 1) * 16 + warp_n * 64);
    const uint32_t x_off_tail = (uint32_t)(((g8 & 1) * 8 + r8) * XBPAD + (g8 >> 1) * 16 + warp_n * 32);

    auto epilogue = [&](int n0, int ntmax) {
        const int row_in = lane >> 2;
        const int col2 = (lane & 3) * 2;
        const int nstride = (ntmax == 4) ? 32 : 16;
        #pragma unroll
        for (int mt = 0; mt < 2; mt++) {
            const int j1 = m0 + warp_m * 32 + mt * 16 + row_in;
            const int j2 = j1 + 8;
            const float c0a = g_c0[j1], cAa = g_cA[j1], cBa = g_cB[j1], cXa = g_cAB[j1];
            const float c0b = g_c0[j2], cAb = g_cA[j2], cBb = g_cB[j2], cXb = g_cAB[j2];
            #pragma unroll
            for (int nt = 0; nt < 4; nt++) {
                if (nt >= ntmax) break;
                const int n = n0 + warp_n * nstride + nt * 8 + col2;
                float2 o1, o2;
                {
                    float A = accA[mt][nt][0], B = accB[mt][nt][0];
                    o1.x = fmaf(cXa * A, B, fmaf(cAa, A, fmaf(cBa, B, c0a)));
                    A = accA[mt][nt][1]; B = accB[mt][nt][1];
                    o1.y = fmaf(cXa * A, B, fmaf(cAa, A, fmaf(cBa, B, c0a)));
                }
                {
                    float A = accA[mt][nt][2], B = accB[mt][nt][2];
                    o2.x = fmaf(cXb * A, B, fmaf(cAb, A, fmaf(cBb, B, c0b)));
                    A = accA[mt][nt][3]; B = accB[mt][nt][3];
                    o2.y = fmaf(cXb * A, B, fmaf(cAb, A, fmaf(cBb, B, c0b)));
                }
                *(float2*)&out[(size_t)j1 * BATCH + n] = o1;
                *(float2*)&out[(size_t)j2 * BATCH + n] = o2;
                #pragma unroll
                for (int e = 0; e < 4; e++) { accA[mt][nt][e] = 0.f; accB[mt][nt][e] = 0.f; }
            }
        }
    };

    // body WITHOUT epilogue (safe under within-quad reordering)
    auto body = [&](int q) {
        const int kt = q & 7;
        const uint32_t xbase = sb + OFF_X + (q & 7) * X_STAGE;
        const uint32_t wkbase = sb + (uint32_t)(kt * BK) * WKPAD + w_off;

        #pragma unroll
        for (int ks = 0; ks < 2; ks++) {
            uint32_t xf[4][2];
            #pragma unroll
            for (int j = 0; j < 2; j++) {
                const uint32_t xo = xbase + x_off + ks * 16 * XBPAD + j * 32;
                uint32_t a0, a1, a2, a3;
                LDSM_X4_T(a0, a1, a2, a3, xo);
                xf[2 * j][0] = a0; xf[2 * j][1] = a1;
                xf[2 * j + 1][0] = a2; xf[2 * j + 1][1] = a3;
            }
            uint32_t fa[2][4], fb[2][4];
            #pragma unroll
            for (int mt = 0; mt < 2; mt++) {
                const uint32_t ao = wkbase + ks * 16 * WKPAD + mt * 32;
                LDSM_X4_T(fa[mt][0], fa[mt][1], fa[mt][2], fa[mt][3], ao);
                LDSM_X4_T(fb[mt][0], fb[mt][1], fb[mt][2], fb[mt][3], ao + W_PROJ);
            }
            #pragma unroll
            for (int mt = 0; mt < 2; mt++) {
                #pragma unroll
                for (int nt = 0; nt < 4; nt++) MMA_F16(accA[mt][nt], fa[mt], xf[nt]);
                #pragma unroll
                for (int nt = 0; nt < 4; nt++) MMA_F16(accB[mt][nt], fb[mt], xf[nt]);
            }
        }
    };

    auto body_tail = [&](int t) {
        const uint32_t xbase = sb + OFF_X + (t & 7) * X_STAGE;
        const uint32_t wkbase = sb + (uint32_t)(t * BK) * WKPAD + w_off;

        #pragma unroll
        for (int ks = 0; ks < 2; ks++) {
            uint32_t xf[2][2];
            {
                const uint32_t xo = xbase + x_off_tail + ks * 16 * XBPAD;
                uint32_t a0, a1, a2, a3;
                LDSM_X4_T(a0, a1, a2, a3, xo);
                xf[0][0] = a0; xf[0][1] = a1;
                xf[1][0] = a2; xf[1][1] = a3;
            }
            uint32_t fa[2][4], fb[2][4];
            #pragma unroll
            for (int mt = 0; mt < 2; mt++) {
                const uint32_t ao = wkbase + ks * 16 * WKPAD + mt * 32;
                LDSM_X4_T(fa[mt][0], fa[mt][1], fa[mt][2], fa[mt][3], ao);
                LDSM_X4_T(fb[mt][0], fb[mt][1], fb[mt][2], fb[mt][3], ao + W_PROJ);
            }
            #pragma unroll
            for (int mt = 0; mt < 2; mt++) {
                #pragma unroll
                for (int nt = 0; nt < 2; nt++) MMA_F16(accA[mt][nt], fa[mt], xf[nt]);
                #pragma unroll
                for (int nt = 0; nt < 2; nt++) MMA_F16(accB[mt][nt], fb[mt], xf[nt]);
            }
        }
    };

    // ---- main loop: quads; each warp processes the quad's 4 steps rotated by warp_m ----
    // Tiles are 8 steps (2 quads), so rotation never crosses a tile; epilogue runs
    // after the quad whose steps are kt 4..7 (q0 & 7 == 4).
    #pragma unroll 1
    for (int q0 = 0; q0 < Q_FULL; q0 += 4) {
        CP_WAIT0();
        __syncthreads();
        issue_stage(q0 + 4); issue_stage(q0 + 5);
        issue_stage(q0 + 6); issue_stage(q0 + 7);
        CP_COMMIT();
        #pragma unroll
        for (int i = 0; i < 4; i++) body(q0 + ((i + warp_m) & 3));
        if ((q0 & 7) == 4) epilogue((nbase + (q0 >> 3) * HALF_CTAS) * BN, 4);
    }

    if (!has_tail) return;

    // ---- tail: 2 quads of half-steps (stages Q_FULL..Q_FULL+7 -> slots t&7) ----
    CP_WAIT0();
    __syncthreads();
    issue_stage(Q_FULL + 4); issue_stage(Q_FULL + 5);
    issue_stage(Q_FULL + 6); issue_stage(Q_FULL + 7);
    CP_COMMIT();
    #pragma unroll
    for (int i = 0; i < 4; i++) body_tail((i + warp_m) & 3);

    CP_WAIT0();
    __syncthreads();
    #pragma unroll
    for (int i = 0; i < 4; i++) body_tail(4 + ((i + warp_m) & 3));
    epilogue(tn0, 2);
}

// ---------------- launch ----------------
extern "C" void kernel_launch(void* const* d_in, const int* in_sizes, int n_in,
                              void* d_out, int out_size) {
    const float* x  = (const float*)d_in[0];   // [PREV,  BATCH]
    const float* wa = (const float*)d_in[1];   // [SIZE,  PREV]
    const float* wb = (const float*)d_in[2];   // [SIZE,  PREV]
    const float* wt = (const float*)d_in[3];   // [16,    SIZE]
    float* out = (float*)d_out;                // [SIZE,  BATCH]

    cudaFuncSetAttribute(fused_logic_mma_kernel,
                         cudaFuncAttributeMaxDynamicSharedMemorySize, SMEM_TOTAL);

    prep_kernel<<<PREP_BLOCKS, 256>>>(wa, wb, wt, x);

    void* xh_dev;
    cudaGetSymbolAddress(&xh_dev, g_xh);
    fused_logic_mma_kernel<<<NCTA, NTHREADS, SMEM_TOTAL>>>((const __half*)xh_dev, out);
}